// round 1
// baseline (speedup 1.0000x reference)
#include <cuda_runtime.h>
#include <cstdint>

#define Nn 2048
#define Dd 64
#define Vv 2048
#define TB 128           // pair tile dim
#define NT (Nn / TB)     // 16 tiles per dim
#define NTILES (NT * (NT + 1) / 2)  // 136 triangle tiles
#define PADK 33          // float2 row stride (pad 1) for conflict-free stride-16 reads

// Scratch (no allocations allowed -> __device__ globals)
__device__ float g_table[(size_t)Vv * Vv];   // fused metric table, 16MB
__device__ unsigned g_maxbits;
__device__ float g_sum, g_cnt;

// ---------------------------------------------------------------------------
__global__ void k_init() { g_maxbits = 0u; g_sum = 0.0f; g_cnt = 0.0f; }

// max over map_dist (values are >= 0, so uint bit compare is order-preserving)
__global__ void k_max(const float4* __restrict__ m) {
    int i = blockIdx.x * blockDim.x + threadIdx.x;
    int stride = gridDim.x * blockDim.x;
    float v = 0.0f;
    for (int idx = i; idx < (Vv * Vv) / 4; idx += stride) {
        float4 x = m[idx];
        v = fmaxf(v, fmaxf(fmaxf(x.x, x.y), fmaxf(x.z, x.w)));
    }
#pragma unroll
    for (int o = 16; o; o >>= 1) v = fmaxf(v, __shfl_xor_sync(0xffffffffu, v, o));
    __shared__ float s[32];
    int lane = threadIdx.x & 31, w = threadIdx.x >> 5;
    if (lane == 0) s[w] = v;
    __syncthreads();
    if (w == 0) {
        v = (lane < (int)(blockDim.x >> 5)) ? s[lane] : 0.0f;
#pragma unroll
        for (int o = 16; o; o >>= 1) v = fmaxf(v, __shfl_xor_sync(0xffffffffu, v, o));
        if (lane == 0) atomicMax(&g_maxbits, __float_as_uint(v));
    }
}

// fused metric table: M = 0.5*tree + (0.5/largest)*map
__global__ void k_table(const float4* __restrict__ tree, const float4* __restrict__ mapd) {
    int i = blockIdx.x * blockDim.x + threadIdx.x;  // V*V/4 threads
    float sc = 0.5f / __uint_as_float(g_maxbits);
    float4 t = tree[i], m = mapd[i];
    float4 o;
    o.x = 0.5f * t.x + sc * m.x;
    o.y = 0.5f * t.y + sc * m.y;
    o.z = 0.5f * t.z + sc * m.z;
    o.w = 0.5f * t.w + sc * m.w;
    ((float4*)g_table)[i] = o;
}

// ---------------------------------------------------------------------------
__device__ __forceinline__ unsigned long long f2add(unsigned long long a,
                                                    unsigned long long b) {
    unsigned long long r;
    asm("add.rn.f32x2 %0, %1, %2;" : "=l"(r) : "l"(a), "l"(b));
    return r;
}

extern __shared__ unsigned long long smem_raw[];

__global__ __launch_bounds__(256, 1) void k_main(const int* __restrict__ ids,
                                                 const float2* __restrict__ emb) {
    // map linear block id -> upper-triangle tile (bi <= bj)
    int t = blockIdx.x, bi = 0;
    while (t >= NT - bi) { t -= NT - bi; bi++; }
    int bj = bi + t;

    unsigned long long* sA = smem_raw;              // [128][PADK] float2-as-u64
    unsigned long long* sB = smem_raw + TB * PADK;  // negated j-tile
    int* sIdI = (int*)(smem_raw + 2 * TB * PADK);
    int* sIdJ = sIdI + TB;

    int tid = threadIdx.x;
    int ibase = bi * TB, jbase = bj * TB;

    // load embedding tiles (coalesced; B negated so diff = packed add)
    for (int x = tid; x < TB * 32; x += 256) {
        int row = x >> 5, k2 = x & 31;
        float2 a = emb[(ibase + row) * 32 + k2];
        float2 b = emb[(jbase + row) * 32 + k2];
        ((float2*)sA)[row * PADK + k2] = a;
        b.x = -b.x; b.y = -b.y;
        ((float2*)sB)[row * PADK + k2] = b;
    }
    if (tid < TB) {
        sIdI[tid] = ids[ibase + tid];
        sIdJ[tid] = ids[jbase + tid];
    }
    __syncthreads();

    int tx = tid & 15, ty = tid >> 4;

    // 8x8 pair tile per thread, cyclic distribution (stride 16) so the
    // stride-16*PADK smem reads land on all 32 banks exactly once.
    unsigned long long acc[8][8];
#pragma unroll
    for (int r = 0; r < 8; r++)
#pragma unroll
        for (int c = 0; c < 8; c++) acc[r][c] = 0ull;

    const unsigned long long ABSM = 0x7FFFFFFF7FFFFFFFull;

#pragma unroll 2
    for (int k2 = 0; k2 < 32; k2++) {
        unsigned long long a2[8], b2[8];
#pragma unroll
        for (int r = 0; r < 8; r++) a2[r] = sA[(ty + 16 * r) * PADK + k2];
#pragma unroll
        for (int c = 0; c < 8; c++) b2[c] = sB[(tx + 16 * c) * PADK + k2];
#pragma unroll
        for (int r = 0; r < 8; r++) {
#pragma unroll
            for (int c = 0; c < 8; c++) {
                unsigned long long d = f2add(a2[r], b2[c]);  // a - b (packed)
                d &= ABSM;                                   // |.| on both halves (ALU pipe)
                acc[r][c] = f2add(acc[r][c], d);
            }
        }
    }

    // gather metric + accumulate loss over strict upper triangle
    float loss = 0.0f, cnt = 0.0f;
    const float inv64 = 1.0f / 64.0f;
#pragma unroll
    for (int r = 0; r < 8; r++) {
        int ir = ty + 16 * r;
        int idi = sIdI[ir];
        int gi = ibase + ir;
        const float* trow = g_table + (size_t)idi * Vv;
#pragma unroll
        for (int c = 0; c < 8; c++) {
            int jc = tx + 16 * c;
            int idj = sIdJ[jc];
            int gj = jbase + jc;
            if (gi < gj && idi != idj) {
                unsigned long long v = acc[r][c];
                float lo = __uint_as_float((unsigned)v);
                float hi = __uint_as_float((unsigned)(v >> 32));
                float ed = (lo + hi) * inv64;
                loss += fabsf(ed - __ldg(trow + idj));
                cnt += 1.0f;
            }
        }
    }

    // block reduce + atomic
#pragma unroll
    for (int o = 16; o; o >>= 1) {
        loss += __shfl_xor_sync(0xffffffffu, loss, o);
        cnt  += __shfl_xor_sync(0xffffffffu, cnt, o);
    }
    __syncthreads();  // done reading sA/sB; reuse as reduction scratch
    float* red = (float*)smem_raw;
    int lane = tid & 31, w = tid >> 5;
    if (lane == 0) { red[w] = loss; red[8 + w] = cnt; }
    __syncthreads();
    if (tid == 0) {
        float L = 0.0f, C = 0.0f;
#pragma unroll
        for (int i = 0; i < 8; i++) { L += red[i]; C += red[8 + i]; }
        atomicAdd(&g_sum, L);
        atomicAdd(&g_cnt, C);
    }
}

__global__ void k_final(float* out) { out[0] = g_sum / g_cnt; }

// ---------------------------------------------------------------------------
extern "C" void kernel_launch(void* const* d_in, const int* in_sizes, int n_in,
                              void* d_out, int out_size) {
    const int*   ids  = (const int*)d_in[0];
    const float* emb  = (const float*)d_in[1];
    const float* tree = (const float*)d_in[2];
    const float* mapd = (const float*)d_in[3];
    float* out = (float*)d_out;

    const int SMEM_BYTES = 2 * TB * PADK * 8 + 2 * TB * 4;  // ~68.6 KB
    cudaFuncSetAttribute(k_main, cudaFuncAttributeMaxDynamicSharedMemorySize,
                         SMEM_BYTES);

    k_init<<<1, 1>>>();
    k_max<<<1024, 256>>>((const float4*)mapd);
    k_table<<<(Vv * Vv / 4) / 256, 256>>>((const float4*)tree, (const float4*)mapd);
    k_main<<<NTILES, 256, SMEM_BYTES>>>(ids, (const float2*)emb);
    k_final<<<1, 1>>>(out);
}

// round 2
// speedup vs baseline: 1.0589x; 1.0589x over previous
#include <cuda_runtime.h>
#include <cstdint>

#define Nn 2048
#define Dd 64
#define Vv 2048
#define TB 128           // pair tile dim
#define NT (Nn / TB)     // 16 tiles per dim
#define NTILES (NT * (NT + 1) / 2)  // 136 triangle tiles
#define PADK 33          // float2 row stride (pad 1) for conflict-free strided reads

// Scratch (no allocations allowed -> __device__ globals)
__device__ float g_table[(size_t)Vv * Vv];   // fused metric table, 16MB
__device__ unsigned g_maxbits;
__device__ float g_sum, g_cnt;

// ---------------------------------------------------------------------------
__global__ void k_init() { g_maxbits = 0u; g_sum = 0.0f; g_cnt = 0.0f; }

// max over map_dist (values are >= 0, so uint bit compare is order-preserving)
__global__ void k_max(const float4* __restrict__ m) {
    int i = blockIdx.x * blockDim.x + threadIdx.x;
    int stride = gridDim.x * blockDim.x;
    float v = 0.0f;
    for (int idx = i; idx < (Vv * Vv) / 4; idx += stride) {
        float4 x = m[idx];
        v = fmaxf(v, fmaxf(fmaxf(x.x, x.y), fmaxf(x.z, x.w)));
    }
#pragma unroll
    for (int o = 16; o; o >>= 1) v = fmaxf(v, __shfl_xor_sync(0xffffffffu, v, o));
    __shared__ float s[32];
    int lane = threadIdx.x & 31, w = threadIdx.x >> 5;
    if (lane == 0) s[w] = v;
    __syncthreads();
    if (w == 0) {
        v = (lane < (int)(blockDim.x >> 5)) ? s[lane] : 0.0f;
#pragma unroll
        for (int o = 16; o; o >>= 1) v = fmaxf(v, __shfl_xor_sync(0xffffffffu, v, o));
        if (lane == 0) atomicMax(&g_maxbits, __float_as_uint(v));
    }
}

// fused metric table: M = 0.5*tree + (0.5/largest)*map
__global__ void k_table(const float4* __restrict__ tree, const float4* __restrict__ mapd) {
    int i = blockIdx.x * blockDim.x + threadIdx.x;  // V*V/4 threads
    float sc = 0.5f / __uint_as_float(g_maxbits);
    float4 t = tree[i], m = mapd[i];
    float4 o;
    o.x = 0.5f * t.x + sc * m.x;
    o.y = 0.5f * t.y + sc * m.y;
    o.z = 0.5f * t.z + sc * m.z;
    o.w = 0.5f * t.w + sc * m.w;
    ((float4*)g_table)[i] = o;
}

// ---------------------------------------------------------------------------
__device__ __forceinline__ unsigned long long f2add(unsigned long long a,
                                                    unsigned long long b) {
    unsigned long long r;
    asm("add.rn.f32x2 %0, %1, %2;" : "=l"(r) : "l"(a), "l"(b));
    return r;
}

extern __shared__ unsigned long long smem_raw[];

// 512 threads: thread (tx = tid&15, ty = tid>>4) owns a 4-row x 8-col pair tile
// rows: ty + 32*r (r<4), cols: tx + 16*c (c<8). Within a warp tx spans 0..15
// twice and ty takes 2 values -> b-loads are 16 distinct stride-33 u64 addrs
// (conflict-free, half-warp multicast), a-loads are 2-addr broadcasts.
__global__ __launch_bounds__(512, 1) void k_main(const int* __restrict__ ids,
                                                 const float2* __restrict__ emb) {
    // map linear block id -> upper-triangle tile (bi <= bj)
    int t = blockIdx.x, bi = 0;
    while (t >= NT - bi) { t -= NT - bi; bi++; }
    int bj = bi + t;

    unsigned long long* sA = smem_raw;              // [128][PADK] float2-as-u64
    unsigned long long* sB = smem_raw + TB * PADK;  // negated j-tile
    int* sIdI = (int*)(smem_raw + 2 * TB * PADK);
    int* sIdJ = sIdI + TB;

    int tid = threadIdx.x;
    int ibase = bi * TB, jbase = bj * TB;

    // load embedding tiles (coalesced; B negated so diff = packed add)
    for (int x = tid; x < TB * 32; x += 512) {
        int row = x >> 5, k2 = x & 31;
        float2 a = emb[(ibase + row) * 32 + k2];
        float2 b = emb[(jbase + row) * 32 + k2];
        ((float2*)sA)[row * PADK + k2] = a;
        b.x = -b.x; b.y = -b.y;
        ((float2*)sB)[row * PADK + k2] = b;
    }
    if (tid < TB) {
        sIdI[tid] = ids[ibase + tid];
        sIdJ[tid] = ids[jbase + tid];
    }
    __syncthreads();

    int tx = tid & 15, ty = tid >> 4;

    unsigned long long acc[4][8];
#pragma unroll
    for (int r = 0; r < 4; r++)
#pragma unroll
        for (int c = 0; c < 8; c++) acc[r][c] = 0ull;

    const unsigned long long ABSM = 0x7FFFFFFF7FFFFFFFull;
    const unsigned long long* sArow = sA + ty * PADK;
    const unsigned long long* sBrow = sB + tx * PADK;

#pragma unroll 4
    for (int k2 = 0; k2 < 32; k2++) {
        unsigned long long a2[4], b2[8];
#pragma unroll
        for (int r = 0; r < 4; r++) a2[r] = sArow[(32 * r) * PADK + k2];
#pragma unroll
        for (int c = 0; c < 8; c++) b2[c] = sBrow[(16 * c) * PADK + k2];
#pragma unroll
        for (int r = 0; r < 4; r++) {
#pragma unroll
            for (int c = 0; c < 8; c++) {
                unsigned long long d = f2add(a2[r], b2[c]);  // a - b (packed)
                d &= ABSM;                                   // |.| both halves (ALU pipe)
                acc[r][c] = f2add(acc[r][c], d);
            }
        }
    }

    // gather metric + accumulate loss over strict upper triangle
    float loss = 0.0f, cnt = 0.0f;
    const float inv64 = 1.0f / 64.0f;
    bool offdiag = (bi != bj);
#pragma unroll
    for (int r = 0; r < 4; r++) {
        int ir = ty + 32 * r;
        int idi = sIdI[ir];
        int gi = ibase + ir;
        const float* trow = g_table + (size_t)idi * Vv;
#pragma unroll
        for (int c = 0; c < 8; c++) {
            int jc = tx + 16 * c;
            int idj = sIdJ[jc];
            int gj = jbase + jc;
            if ((offdiag || gi < gj) && idi != idj) {
                unsigned long long v = acc[r][c];
                float lo = __uint_as_float((unsigned)v);
                float hi = __uint_as_float((unsigned)(v >> 32));
                float ed = (lo + hi) * inv64;
                loss += fabsf(ed - __ldg(trow + idj));
                cnt += 1.0f;
            }
        }
    }

    // block reduce + atomic
#pragma unroll
    for (int o = 16; o; o >>= 1) {
        loss += __shfl_xor_sync(0xffffffffu, loss, o);
        cnt  += __shfl_xor_sync(0xffffffffu, cnt, o);
    }
    __syncthreads();  // done reading sA/sB; reuse as reduction scratch
    float* red = (float*)smem_raw;
    int lane = tid & 31, w = tid >> 5;
    if (lane == 0) { red[w] = loss; red[16 + w] = cnt; }
    __syncthreads();
    if (tid == 0) {
        float L = 0.0f, C = 0.0f;
#pragma unroll
        for (int i = 0; i < 16; i++) { L += red[i]; C += red[16 + i]; }
        atomicAdd(&g_sum, L);
        atomicAdd(&g_cnt, C);
    }
}

__global__ void k_final(float* out) { out[0] = g_sum / g_cnt; }

// ---------------------------------------------------------------------------
extern "C" void kernel_launch(void* const* d_in, const int* in_sizes, int n_in,
                              void* d_out, int out_size) {
    const int*   ids  = (const int*)d_in[0];
    const float* emb  = (const float*)d_in[1];
    const float* tree = (const float*)d_in[2];
    const float* mapd = (const float*)d_in[3];
    float* out = (float*)d_out;

    const int SMEM_BYTES = 2 * TB * PADK * 8 + 2 * TB * 4;  // ~68.6 KB
    cudaFuncSetAttribute(k_main, cudaFuncAttributeMaxDynamicSharedMemorySize,
                         SMEM_BYTES);

    k_init<<<1, 1>>>();
    k_max<<<1024, 256>>>((const float4*)mapd);
    k_table<<<(Vv * Vv / 4) / 256, 256>>>((const float4*)tree, (const float4*)mapd);
    k_main<<<NTILES, 512, SMEM_BYTES>>>(ids, (const float2*)emb);
    k_final<<<1, 1>>>(out);
}